// round 16
// baseline (speedup 1.0000x reference)
#include <cuda_runtime.h>
#include <cuda_fp16.h>
#include <mma.h>
#include <cstdint>

using namespace nvcuda;

#define HID    1024
#define NHEADS 16
#define HDIM   64
#define BATCH  8
#define SEQ    1024
#define MROWS  (BATCH*SEQ)        // 8192
#define BHS    (BATCH*NHEADS*SEQ) // 131072

// Scratch (device globals — no allocation allowed)
__device__ __half g_Qh[MROWS*HID];
__device__ __half g_Kh[MROWS*HID];
__device__ __half g_Vh[MROWS*HID];
__device__ __half g_Oh[MROWS*HID];
// fp16 copies of raw inputs / weights
__device__ __half g_Xq[MROWS*HID];
__device__ __half g_Xk[MROWS*HID];
__device__ __half g_Xv[MROWS*HID];
__device__ __half g_Wqh[HID*HID];
__device__ __half g_Wkh[HID*HID];
__device__ __half g_Wvh[HID*HID];
__device__ __half g_Woh[HID*HID];

// ---------------------------------------------------------------------------
// cp.async / ldmatrix / mma helpers
// ---------------------------------------------------------------------------
__device__ __forceinline__ void cp_async16(void* smem, const void* gmem){
    unsigned s = (unsigned)__cvta_generic_to_shared(smem);
    asm volatile("cp.async.cg.shared.global [%0], [%1], 16;\n" :: "r"(s), "l"(gmem));
}
#define CP_COMMIT()  asm volatile("cp.async.commit_group;\n" ::: "memory")
#define CP_WAIT0()   asm volatile("cp.async.wait_group 0;\n" ::: "memory")

#define LDMX4(r0,r1,r2,r3,addr) \
    asm volatile("ldmatrix.sync.aligned.m8n8.x4.shared.b16 {%0,%1,%2,%3}, [%4];" \
        : "=r"(r0), "=r"(r1), "=r"(r2), "=r"(r3) : "r"(addr))

#define LDMX2T(r0,r1,addr) \
    asm volatile("ldmatrix.sync.aligned.m8n8.x2.trans.shared.b16 {%0,%1}, [%2];" \
        : "=r"(r0), "=r"(r1) : "r"(addr))

#define MMA16816(d, a0,a1,a2,a3, b0,b1) \
    asm volatile("mma.sync.aligned.m16n8k16.row.col.f32.f16.f16.f32 " \
        "{%0,%1,%2,%3}, {%4,%5,%6,%7}, {%8,%9}, {%0,%1,%2,%3};" \
        : "+f"((d)[0]), "+f"((d)[1]), "+f"((d)[2]), "+f"((d)[3]) \
        : "r"(a0), "r"(a1), "r"(a2), "r"(a3), "r"(b0), "r"(b1))

// ---------------------------------------------------------------------------
// fp32 -> fp16 conversion kernels (8 elements per thread)
// ---------------------------------------------------------------------------
__device__ __forceinline__ void cvt8(const float* in, __half* out, size_t i){
    float4 v0 = *(const float4*)(in + i);
    float4 v1 = *(const float4*)(in + i + 4);
    __half2 h0 = __floats2half2_rn(v0.x, v0.y);
    __half2 h1 = __floats2half2_rn(v0.z, v0.w);
    __half2 h2 = __floats2half2_rn(v1.x, v1.y);
    __half2 h3 = __floats2half2_rn(v1.z, v1.w);
    uint4 u;
    u.x = *(unsigned*)&h0; u.y = *(unsigned*)&h1;
    u.z = *(unsigned*)&h2; u.w = *(unsigned*)&h3;
    *(uint4*)(out + i) = u;
}

__global__ void __launch_bounds__(256)
cvt_act_kernel(const float* __restrict__ a0, const float* __restrict__ a1,
               const float* __restrict__ a2,
               __half* __restrict__ o0, __half* __restrict__ o1,
               __half* __restrict__ o2)
{
    const int z = blockIdx.z;
    const float* in  = (z==0) ? a0 : (z==1) ? a1 : a2;
    __half*      out = (z==0) ? o0 : (z==1) ? o1 : o2;
    cvt8(in, out, ((size_t)blockIdx.x*256 + threadIdx.x)*8);
}

__global__ void __launch_bounds__(256)
cvt_w_kernel(const float* __restrict__ w0, const float* __restrict__ w1,
             const float* __restrict__ w2, const float* __restrict__ w3,
             __half* __restrict__ o0, __half* __restrict__ o1,
             __half* __restrict__ o2, __half* __restrict__ o3)
{
    const int z = blockIdx.z;
    const float* in  = (z==0) ? w0 : (z==1) ? w1 : (z==2) ? w2 : w3;
    __half*      out = (z==0) ? o0 : (z==1) ? o1 : (z==2) ? o2 : o3;
    cvt8(in, out, ((size_t)blockIdx.x*256 + threadIdx.x)*8);
}

// ===========================================================================
// fp16 projection (unchanged — proven): C = (A @ W^T + bias)*scale
// ===========================================================================
#define TBM 128
#define TBN 128
#define TBK 64
#define LDTH 72
#define PT_TILE (TBM*LDTH*2)             // 18432 B per buffer
#define EPLD 132
#define PROJ_SMEM_BYTES (4*PT_TILE)      // 73728

__device__ __forceinline__
void proj_body_h(const __half* __restrict__ A, const __half* __restrict__ W,
                 const float* __restrict__ bias, float scale,
                 float* __restrict__ Cf, __half* __restrict__ Ch,
                 char* smem)
{
    char* sAb[2] = { smem,             smem + 2*PT_TILE };
    char* sBb[2] = { smem + PT_TILE,   smem + 3*PT_TILE };

    const int tid  = threadIdx.x;
    const int warp = tid >> 5;
    const int wm   = warp & 3;
    const int wn   = warp >> 2;
    const int m0   = blockIdx.y * TBM;
    const int n0   = blockIdx.x * TBN;

    wmma::fragment<wmma::accumulator,16,16,16,float> acc[2][4];
    #pragma unroll
    for (int mi=0;mi<2;mi++)
        #pragma unroll
        for (int ni=0;ni<4;ni++)
            wmma::fill_fragment(acc[mi][ni], 0.0f);

    {
        #pragma unroll
        for (int p=0;p<4;p++){
            const int idx = tid + p*256;
            const int r   = idx >> 3;
            const int ch  = idx & 7;
            cp_async16(sAb[0] + r*144 + ch*16, A + (size_t)(m0 + r)*HID + ch*8);
            cp_async16(sBb[0] + r*144 + ch*16, W + (size_t)(n0 + r)*HID + ch*8);
        }
        CP_COMMIT();
    }

    const int NKT = HID / TBK;  // 16
    for (int kt=0; kt<NKT; kt++){
        CP_WAIT0();
        __syncthreads();
        if (kt+1 < NKT){
            const int k0 = (kt+1)*TBK;
            char* Ad = sAb[(kt+1)&1];
            char* Bd = sBb[(kt+1)&1];
            #pragma unroll
            for (int p=0;p<4;p++){
                const int idx = tid + p*256;
                const int r   = idx >> 3;
                const int ch  = idx & 7;
                cp_async16(Ad + r*144 + ch*16, A + (size_t)(m0 + r)*HID + k0 + ch*8);
                cp_async16(Bd + r*144 + ch*16, W + (size_t)(n0 + r)*HID + k0 + ch*8);
            }
            CP_COMMIT();
        }
        const __half* As = (const __half*)sAb[kt&1];
        const __half* Bs = (const __half*)sBb[kt&1];
        #pragma unroll
        for (int kk=0; kk<TBK; kk+=16){
            wmma::fragment<wmma::matrix_a,16,16,16,__half,wmma::row_major> af[2];
            wmma::fragment<wmma::matrix_b,16,16,16,__half,wmma::col_major> bf[4];
            #pragma unroll
            for (int mi=0;mi<2;mi++)
                wmma::load_matrix_sync(af[mi], As + (wm*32+mi*16)*LDTH + kk, LDTH);
            #pragma unroll
            for (int ni=0;ni<4;ni++)
                wmma::load_matrix_sync(bf[ni], Bs + (wn*64+ni*16)*LDTH + kk, LDTH);
            #pragma unroll
            for (int mi=0;mi<2;mi++)
                #pragma unroll
                for (int ni=0;ni<4;ni++)
                    wmma::mma_sync(acc[mi][ni], af[mi], bf[ni], acc[mi][ni]);
        }
    }

    __syncthreads();
    float* ep = (float*)smem;
    #pragma unroll
    for (int mi=0;mi<2;mi++)
        #pragma unroll
        for (int ni=0;ni<4;ni++)
            wmma::store_matrix_sync(ep + (wm*32+mi*16)*EPLD + wn*64 + ni*16,
                                    acc[mi][ni], EPLD, wmma::mem_row_major);
    __syncthreads();
    {
        const int er  = tid >> 5;
        const int ec4 = (tid & 31) * 4;
        float4 bb = *(const float4*)(bias + n0 + ec4);
        #pragma unroll
        for (int p=0;p<16;p++){
            int r = p*8 + er;
            float4 v = *(float4*)(ep + r*EPLD + ec4);
            v.x = (v.x + bb.x) * scale;
            v.y = (v.y + bb.y) * scale;
            v.z = (v.z + bb.z) * scale;
            v.w = (v.w + bb.w) * scale;
            if (Ch){
                __half2 h0 = __floats2half2_rn(v.x, v.y);
                __half2 h1 = __floats2half2_rn(v.z, v.w);
                __half2* dst = (__half2*)(Ch + (size_t)(m0 + r)*HID + n0 + ec4);
                dst[0] = h0; dst[1] = h1;
            } else {
                *(float4*)(Cf + (size_t)(m0 + r)*HID + n0 + ec4) = v;
            }
        }
    }
}

__global__ void __launch_bounds__(256,2)
qkv_proj_kernel(const float* __restrict__ bq, const float* __restrict__ bk,
                const float* __restrict__ bv)
{
    extern __shared__ char smem[];
    const int z = blockIdx.z;
    const __half* A    = (z==0) ? g_Xq  : (z==1) ? g_Xk  : g_Xv;
    const __half* W    = (z==0) ? g_Wqh : (z==1) ? g_Wkh : g_Wvh;
    const float* bias  = (z==0) ? bq : (z==1) ? bk : bv;
    __half*      C     = (z==0) ? g_Qh : (z==1) ? g_Kh : g_Vh;
    const float scale  = (z==0) ? 0.125f : 1.0f;
    proj_body_h(A, W, bias, scale, nullptr, C, smem);
}

__global__ void __launch_bounds__(256,2)
out_proj_kernel(const float* __restrict__ bo, float* __restrict__ C)
{
    extern __shared__ char smem[];
    proj_body_h(g_Oh, g_Woh, bo, 1.0f, C, nullptr, smem);
}

// ===========================================================================
// Single-pass FA attention, deferred normalization, raw mma.sync + ldmatrix.
// CTA = 256 threads (8 warps), 32 query rows of one (b,h), 2 CTAs/SM.
// Per chunk: QK once -> exp (unnormalized, masked) -> row sums in regs ->
//   fp16 P_un into persistent SMEM P (32x1024, stride 2064B) -> PV with P_un.
// End: rowI = 1/sums; O = O_un * rowI (registers); attn = float(P_un)*rowI.
// ===========================================================================
#define STRIPE 32
#define CH     64
#define NCHUNK (SEQ/CH)        // 16
#define LDPB   2064            // P row stride in bytes (129 * 16B, conflict-free)
// SMEM layout (bytes); K/V/Q rows are 144 B (72 halves)
#define AS_Q    0                      // 32*144  = 4608
#define AS_K    4608                   // 2*64*144 = 18432
#define AS_V    23040                  // 2*64*144 = 18432
#define AS_P    41472                  // 32*2064 = 66048
#define AS_M    107520                 // 4096
#define AS_SP   111616                 // 4*32 floats = 512
#define AS_RI   112128                 // 32 floats = 128
#define FUSED_SMEM_BYTES 112256

__global__ void __launch_bounds__(256,2)
fused_attn_kernel(float* __restrict__ attn, const int* __restrict__ mask)
{
    extern __shared__ char smc[];
    const unsigned sbase = (unsigned)__cvta_generic_to_shared(smc);

    const int tid  = threadIdx.x;
    const int warp = tid >> 5;
    const int lane = tid & 31;
    const int wm   = warp & 1;
    const int wn   = warp >> 1;          // 0..3

    const int blk  = blockIdx.x;
    const int bh   = blk >> 5;
    const int strp = blk & 31;
    const int b    = bh >> 4;
    const int h    = bh & 15;
    const int m0   = strp * STRIPE;

    const __half* Qb = g_Qh + ((size_t)b*SEQ + m0)*HID + h*HDIM;
    const __half* Kg = g_Kh + (size_t)b*SEQ*HID + h*HDIM;
    const __half* Vg = g_Vh + (size_t)b*SEQ*HID + h*HDIM;

    // ---- fills: mask (plain stores), Q stripe + K0 + V0 (cp.async) ----
    *(int4*)(smc + AS_M + tid*16) = ((const int4*)(mask + b*SEQ))[tid];
    {
        const int r  = tid >> 3;
        const int ch = tid & 7;
        cp_async16(smc + AS_Q + r*144 + ch*16, Qb + (size_t)r*HID + ch*8);
        #pragma unroll
        for (int p=0;p<2;p++){
            const int idx = tid + p*256;
            const int kr  = idx >> 3;
            const int kc  = idx & 7;
            cp_async16(smc + AS_K + kr*144 + kc*16, Kg + (size_t)kr*HID + kc*8);
            cp_async16(smc + AS_V + kr*144 + kc*16, Vg + (size_t)kr*HID + kc*8);
        }
        CP_COMMIT();
    }
    CP_WAIT0();
    __syncthreads();

    // ---- mask bitset per lane ----
    uint64_t mb = 0;
    {
        const int* Msp = (const int*)(smc + AS_M);
        const int cb = wn*16 + (lane&3)*2;
        #pragma unroll
        for (int c=0;c<NCHUNK;c++)
            #pragma unroll
            for (int t=0;t<2;t++)
                #pragma unroll
                for (int j=0;j<2;j++)
                    if (Msp[c*64 + cb + t*8 + j])
                        mb |= 1ull << (c*4 + t*2 + j);
    }

    // ---- Q fragments: loaded ONCE ----
    const int qrow = (lane & 7) + ((lane >> 3) & 1)*8;
    const int qcB  = ((lane >> 4) & 1)*16;
    unsigned qa[4][4];
    {
        const unsigned qaddr = sbase + AS_Q + (wm*16 + qrow)*144 + qcB;
        #pragma unroll
        for (int s=0;s<4;s++)
            LDMX4(qa[s][0], qa[s][1], qa[s][2], qa[s][3], qaddr + s*32);
    }

    // K ldmatrix lane addressing
    const int knoff = (lane & 7) | ((lane >> 1) & 8);
    const int kB    = ((lane >> 3) & 1)*16;
    const unsigned kbase_l = (wn*16 + knoff)*144 + kB;

    const int vrow = (lane & 7) + ((lane >> 3) & 1)*8;
    const int grow = wm*16 + (lane>>2);
    const int colb = wn*16 + (lane&3)*2;

    float s0 = 0.0f, s1 = 0.0f;          // unnormalized row sums
    float oacc0[4] = {0,0,0,0};          // O_un, rows grow / grow+8, cols wn*16..+7
    float oacc1[4] = {0,0,0,0};          // cols wn*16+8..+15

    // ================= single pass over chunks =================
    for (int c=0;c<NCHUNK;c++){
        if (c+1 < NCHUNK){
            const __half* ksrc = Kg + (size_t)((c+1)*CH)*HID;
            const __half* vsrc = Vg + (size_t)((c+1)*CH)*HID;
            char* kdst = smc + AS_K + ((c+1)&1)*9216;
            char* vdst = smc + AS_V + ((c+1)&1)*9216;
            #pragma unroll
            for (int p=0;p<2;p++){
                const int idx = tid + p*256;
                const int kr  = idx >> 3;
                const int kc  = idx & 7;
                cp_async16(kdst + kr*144 + kc*16, ksrc + (size_t)kr*HID + kc*8);
                cp_async16(vdst + kr*144 + kc*16, vsrc + (size_t)kr*HID + kc*8);
            }
            CP_COMMIT();
        }

        // QK for this warp's 16x16 tile
        const unsigned kaddr = sbase + AS_K + (c&1)*9216 + kbase_l;
        float acc0[4] = {0,0,0,0};
        float acc1[4] = {0,0,0,0};
        #pragma unroll
        for (int s=0;s<4;s++){
            unsigned k0,k1,k2,k3;
            LDMX4(k0,k1,k2,k3, kaddr + s*32);
            MMA16816(acc0, qa[s][0],qa[s][1],qa[s][2],qa[s][3], k0,k1);
            MMA16816(acc1, qa[s][0],qa[s][1],qa[s][2],qa[s][3], k2,k3);
        }

        // exp (unnormalized), mask, sums, fp16 pack into persistent P
        {
            const unsigned mbits = (unsigned)(mb >> (c*4)) & 0xFu;
            float p00 = (mbits & 1u) ? __expf(acc0[0]) : 0.0f;
            float p01 = (mbits & 2u) ? __expf(acc0[1]) : 0.0f;
            float p02 = (mbits & 1u) ? __expf(acc0[2]) : 0.0f;
            float p03 = (mbits & 2u) ? __expf(acc0[3]) : 0.0f;
            float p10 = (mbits & 4u) ? __expf(acc1[0]) : 0.0f;
            float p11 = (mbits & 8u) ? __expf(acc1[1]) : 0.0f;
            float p12 = (mbits & 4u) ? __expf(acc1[2]) : 0.0f;
            float p13 = (mbits & 8u) ? __expf(acc1[3]) : 0.0f;
            s0 += (p00 + p01) + (p10 + p11);
            s1 += (p02 + p03) + (p12 + p13);
            __half2 h0 = __floats2half2_rn(p00, p01);
            __half2 h1 = __floats2half2_rn(p02, p03);
            __half2 h2 = __floats2half2_rn(p10, p11);
            __half2 h3 = __floats2half2_rn(p12, p13);
            const unsigned pb = (unsigned)(c*64 + colb)*2;
            *(__half2*)(smc + AS_P + grow*LDPB     + pb)      = h0;
            *(__half2*)(smc + AS_P + (grow+8)*LDPB + pb)      = h1;
            *(__half2*)(smc + AS_P + grow*LDPB     + pb + 16) = h2;
            *(__half2*)(smc + AS_P + (grow+8)*LDPB + pb + 16) = h3;
        }
        __syncthreads();   // P[c] tile complete (all wn warps)

        // PV: O_un[wm rows, wn 16-cols] += P_un(16 x 64) @ V(64, wn-slice)
        {
            const unsigned paddr = sbase + AS_P + (wm*16 + qrow)*LDPB + c*128 + qcB;
            const unsigned vbase = sbase + AS_V + (c&1)*9216;
            #pragma unroll
            for (int kk=0;kk<4;kk++){
                unsigned p0,p1,p2,p3;
                LDMX4(p0,p1,p2,p3, paddr + kk*32);
                unsigned v0,v1,w0,w1;
                LDMX2T(v0,v1, vbase + (kk*16+vrow)*144 + wn*32);
                LDMX2T(w0,w1, vbase + (kk*16+vrow)*144 + wn*32 + 16);
                MMA16816(oacc0, p0,p1,p2,p3, v0,v1);
                MMA16816(oacc1, p0,p1,p2,p3, w0,w1);
            }
        }
        CP_WAIT0();
        __syncthreads();   // K/V[c+1] ready; K/V[c] free for overwrite at c+2
    }

    // ---- row-sum reduction -> rowI ----
    s0 += __shfl_xor_sync(0xffffffffu, s0, 1);
    s0 += __shfl_xor_sync(0xffffffffu, s0, 2);
    s1 += __shfl_xor_sync(0xffffffffu, s1, 1);
    s1 += __shfl_xor_sync(0xffffffffu, s1, 2);
    float* Sp   = (float*)(smc + AS_SP);
    float* rowI = (float*)(smc + AS_RI);
    if ((lane & 3) == 0){
        Sp[wn*32 + wm*16 +     (lane>>2)] = s0;
        Sp[wn*32 + wm*16 + 8 + (lane>>2)] = s1;
    }
    __syncthreads();
    if (tid < 32)
        rowI[tid] = 1.0f / (Sp[tid] + Sp[32+tid] + Sp[64+tid] + Sp[96+tid]);
    __syncthreads();

    // ---- O = O_un * rowI ; store fp16 (each warp owns disjoint 16x16) ----
    {
        const float rI0 = rowI[grow];
        const float rI1 = rowI[grow + 8];
        __half2 a0 = __floats2half2_rn(oacc0[0]*rI0, oacc0[1]*rI0);
        __half2 a1 = __floats2half2_rn(oacc0[2]*rI1, oacc0[3]*rI1);
        __half2 a2 = __floats2half2_rn(oacc1[0]*rI0, oacc1[1]*rI0);
        __half2 a3 = __floats2half2_rn(oacc1[2]*rI1, oacc1[3]*rI1);
        __half* base0 = g_Oh + (size_t)(b*SEQ + m0 + grow)*HID + h*HDIM;
        __half* base1 = g_Oh + (size_t)(b*SEQ + m0 + grow + 8)*HID + h*HDIM;
        *(__half2*)(base0 + colb)     = a0;
        *(__half2*)(base1 + colb)     = a1;
        *(__half2*)(base0 + colb + 8) = a2;
        *(__half2*)(base1 + colb + 8) = a3;
    }

    // ---- attention output: attn = float(P_un) * rowI, coalesced ----
    {
        const int r  = tid >> 3;               // 0..31
        const int cb = (tid & 7) * 4;          // col base (floats)
        const float rI = rowI[r];
        const __half* prow = (const __half*)(smc + AS_P + r*LDPB);
        float* arow = attn + ((size_t)bh*SEQ + m0 + r)*SEQ;
        #pragma unroll
        for (int j=0;j<32;j++){
            const int col = cb + j*32;
            __half2 hA = *(const __half2*)(prow + col);
            __half2 hB = *(const __half2*)(prow + col + 2);
            float2 fA = __half22float2(hA);
            float2 fB = __half22float2(hB);
            *(float4*)(arow + col) =
                make_float4(fA.x*rI, fA.y*rI, fB.x*rI, fB.y*rI);
        }
    }
}

// ---------------------------------------------------------------------------
extern "C" void kernel_launch(void* const* d_in, const int* in_sizes, int n_in,
                              void* d_out, int out_size)
{
    const float* query = (const float*)d_in[0];
    const float* key   = (const float*)d_in[1];
    const float* value = (const float*)d_in[2];
    const float* Wq    = (const float*)d_in[3];
    const float* bq    = (const float*)d_in[4];
    const float* Wk    = (const float*)d_in[5];
    const float* bk    = (const float*)d_in[6];
    const float* Wv    = (const float*)d_in[7];
    const float* bv    = (const float*)d_in[8];
    const float* Wo    = (const float*)d_in[9];
    const float* bo    = (const float*)d_in[10];
    const int*   mask  = (const int*)d_in[11];

    float* out_x = (float*)d_out;
    float* attn  = out_x + (size_t)MROWS * HID;

    __half *xq, *xk, *xv, *wqh, *wkh, *wvh, *woh;
    cudaGetSymbolAddress((void**)&xq, g_Xq);
    cudaGetSymbolAddress((void**)&xk, g_Xk);
    cudaGetSymbolAddress((void**)&xv, g_Xv);
    cudaGetSymbolAddress((void**)&wqh, g_Wqh);
    cudaGetSymbolAddress((void**)&wkh, g_Wkh);
    cudaGetSymbolAddress((void**)&wvh, g_Wvh);
    cudaGetSymbolAddress((void**)&woh, g_Woh);

    static int attr_done = 0;
    if (!attr_done){
        cudaFuncSetAttribute(qkv_proj_kernel,
            cudaFuncAttributeMaxDynamicSharedMemorySize, PROJ_SMEM_BYTES);
        cudaFuncSetAttribute(out_proj_kernel,
            cudaFuncAttributeMaxDynamicSharedMemorySize, PROJ_SMEM_BYTES);
        cudaFuncSetAttribute(fused_attn_kernel,
            cudaFuncAttributeMaxDynamicSharedMemorySize, FUSED_SMEM_BYTES);
        attr_done = 1;
    }

    // fp32 -> fp16 conversions (inputs + weights)
    dim3 gact(MROWS*HID/(256*8), 1, 3);   // (4096,1,3)
    dim3 gw(HID*HID/(256*8), 1, 4);       // (512,1,4)
    cvt_act_kernel<<<gact, 256>>>(query, key, value, xq, xk, xv);
    cvt_w_kernel<<<gw, 256>>>(Wq, Wk, Wv, Wo, wqh, wkh, wvh, woh);

    dim3 gqkv(HID/TBN, MROWS/TBM, 3);   // (8, 64, 3)
    dim3 gproj(HID/TBN, MROWS/TBM);     // (8, 64)

    // Q/K/V projections (1/sqrt(64) folded into Q); half outputs
    qkv_proj_kernel<<<gqkv, 256, PROJ_SMEM_BYTES>>>(bq, bk, bv);

    // Single-pass fused attention (attention to d_out)
    fused_attn_kernel<<<BHS/STRIPE, 256, FUSED_SMEM_BYTES>>>(attn, mask);

    // x = O Wo^T + bo (exact fp32 output)
    out_proj_kernel<<<gproj, 256, PROJ_SMEM_BYTES>>>(bo, out_x);
}

// round 17
// speedup vs baseline: 1.4123x; 1.4123x over previous
#include <cuda_runtime.h>
#include <cuda_fp16.h>
#include <mma.h>
#include <cstdint>

using namespace nvcuda;

#define HID    1024
#define NHEADS 16
#define HDIM   64
#define BATCH  8
#define SEQ    1024
#define MROWS  (BATCH*SEQ)        // 8192
#define BHS    (BATCH*NHEADS*SEQ) // 131072

// Scratch (device globals — no allocation allowed)
__device__ __half g_Qh[MROWS*HID];
__device__ __half g_Kh[MROWS*HID];
__device__ __half g_Vh[MROWS*HID];
__device__ __half g_Oh[MROWS*HID];
// fp16 copies of raw inputs / weights
__device__ __half g_Xq[MROWS*HID];
__device__ __half g_Xk[MROWS*HID];
__device__ __half g_Xv[MROWS*HID];
__device__ __half g_Wqh[HID*HID];
__device__ __half g_Wkh[HID*HID];
__device__ __half g_Wvh[HID*HID];
__device__ __half g_Woh[HID*HID];

// ---------------------------------------------------------------------------
// cp.async / ldmatrix / mma helpers
// ---------------------------------------------------------------------------
__device__ __forceinline__ void cp_async16(void* smem, const void* gmem){
    unsigned s = (unsigned)__cvta_generic_to_shared(smem);
    asm volatile("cp.async.cg.shared.global [%0], [%1], 16;\n" :: "r"(s), "l"(gmem));
}
#define CP_COMMIT()  asm volatile("cp.async.commit_group;\n" ::: "memory")
#define CP_WAIT0()   asm volatile("cp.async.wait_group 0;\n" ::: "memory")

#define LDMX4(r0,r1,r2,r3,addr) \
    asm volatile("ldmatrix.sync.aligned.m8n8.x4.shared.b16 {%0,%1,%2,%3}, [%4];" \
        : "=r"(r0), "=r"(r1), "=r"(r2), "=r"(r3) : "r"(addr))

#define LDMX2T(r0,r1,addr) \
    asm volatile("ldmatrix.sync.aligned.m8n8.x2.trans.shared.b16 {%0,%1}, [%2];" \
        : "=r"(r0), "=r"(r1) : "r"(addr))

#define MMA16816(d, a0,a1,a2,a3, b0,b1) \
    asm volatile("mma.sync.aligned.m16n8k16.row.col.f32.f16.f16.f32 " \
        "{%0,%1,%2,%3}, {%4,%5,%6,%7}, {%8,%9}, {%0,%1,%2,%3};" \
        : "+f"((d)[0]), "+f"((d)[1]), "+f"((d)[2]), "+f"((d)[3]) \
        : "r"(a0), "r"(a1), "r"(a2), "r"(a3), "r"(b0), "r"(b1))

// ---------------------------------------------------------------------------
// fp32 -> fp16 conversion kernels (8 elements per thread)
// ---------------------------------------------------------------------------
__device__ __forceinline__ void cvt8(const float* in, __half* out, size_t i){
    float4 v0 = *(const float4*)(in + i);
    float4 v1 = *(const float4*)(in + i + 4);
    __half2 h0 = __floats2half2_rn(v0.x, v0.y);
    __half2 h1 = __floats2half2_rn(v0.z, v0.w);
    __half2 h2 = __floats2half2_rn(v1.x, v1.y);
    __half2 h3 = __floats2half2_rn(v1.z, v1.w);
    uint4 u;
    u.x = *(unsigned*)&h0; u.y = *(unsigned*)&h1;
    u.z = *(unsigned*)&h2; u.w = *(unsigned*)&h3;
    *(uint4*)(out + i) = u;
}

__global__ void __launch_bounds__(256)
cvt_act_kernel(const float* __restrict__ a0, const float* __restrict__ a1,
               const float* __restrict__ a2,
               __half* __restrict__ o0, __half* __restrict__ o1,
               __half* __restrict__ o2)
{
    const int z = blockIdx.z;
    const float* in  = (z==0) ? a0 : (z==1) ? a1 : a2;
    __half*      out = (z==0) ? o0 : (z==1) ? o1 : o2;
    cvt8(in, out, ((size_t)blockIdx.x*256 + threadIdx.x)*8);
}

__global__ void __launch_bounds__(256)
cvt_w_kernel(const float* __restrict__ w0, const float* __restrict__ w1,
             const float* __restrict__ w2, const float* __restrict__ w3,
             __half* __restrict__ o0, __half* __restrict__ o1,
             __half* __restrict__ o2, __half* __restrict__ o3)
{
    const int z = blockIdx.z;
    const float* in  = (z==0) ? w0 : (z==1) ? w1 : (z==2) ? w2 : w3;
    __half*      out = (z==0) ? o0 : (z==1) ? o1 : (z==2) ? o2 : o3;
    cvt8(in, out, ((size_t)blockIdx.x*256 + threadIdx.x)*8);
}

// ===========================================================================
// fp16 projection (unchanged — proven): C = (A @ W^T + bias)*scale
// ===========================================================================
#define TBM 128
#define TBN 128
#define TBK 64
#define LDTH 72
#define PT_TILE (TBM*LDTH*2)             // 18432 B per buffer
#define EPLD 132
#define PROJ_SMEM_BYTES (4*PT_TILE)      // 73728

__device__ __forceinline__
void proj_body_h(const __half* __restrict__ A, const __half* __restrict__ W,
                 const float* __restrict__ bias, float scale,
                 float* __restrict__ Cf, __half* __restrict__ Ch,
                 char* smem)
{
    char* sAb[2] = { smem,             smem + 2*PT_TILE };
    char* sBb[2] = { smem + PT_TILE,   smem + 3*PT_TILE };

    const int tid  = threadIdx.x;
    const int warp = tid >> 5;
    const int wm   = warp & 3;
    const int wn   = warp >> 2;
    const int m0   = blockIdx.y * TBM;
    const int n0   = blockIdx.x * TBN;

    wmma::fragment<wmma::accumulator,16,16,16,float> acc[2][4];
    #pragma unroll
    for (int mi=0;mi<2;mi++)
        #pragma unroll
        for (int ni=0;ni<4;ni++)
            wmma::fill_fragment(acc[mi][ni], 0.0f);

    {
        #pragma unroll
        for (int p=0;p<4;p++){
            const int idx = tid + p*256;
            const int r   = idx >> 3;
            const int ch  = idx & 7;
            cp_async16(sAb[0] + r*144 + ch*16, A + (size_t)(m0 + r)*HID + ch*8);
            cp_async16(sBb[0] + r*144 + ch*16, W + (size_t)(n0 + r)*HID + ch*8);
        }
        CP_COMMIT();
    }

    const int NKT = HID / TBK;  // 16
    for (int kt=0; kt<NKT; kt++){
        CP_WAIT0();
        __syncthreads();
        if (kt+1 < NKT){
            const int k0 = (kt+1)*TBK;
            char* Ad = sAb[(kt+1)&1];
            char* Bd = sBb[(kt+1)&1];
            #pragma unroll
            for (int p=0;p<4;p++){
                const int idx = tid + p*256;
                const int r   = idx >> 3;
                const int ch  = idx & 7;
                cp_async16(Ad + r*144 + ch*16, A + (size_t)(m0 + r)*HID + k0 + ch*8);
                cp_async16(Bd + r*144 + ch*16, W + (size_t)(n0 + r)*HID + k0 + ch*8);
            }
            CP_COMMIT();
        }
        const __half* As = (const __half*)sAb[kt&1];
        const __half* Bs = (const __half*)sBb[kt&1];
        #pragma unroll
        for (int kk=0; kk<TBK; kk+=16){
            wmma::fragment<wmma::matrix_a,16,16,16,__half,wmma::row_major> af[2];
            wmma::fragment<wmma::matrix_b,16,16,16,__half,wmma::col_major> bf[4];
            #pragma unroll
            for (int mi=0;mi<2;mi++)
                wmma::load_matrix_sync(af[mi], As + (wm*32+mi*16)*LDTH + kk, LDTH);
            #pragma unroll
            for (int ni=0;ni<4;ni++)
                wmma::load_matrix_sync(bf[ni], Bs + (wn*64+ni*16)*LDTH + kk, LDTH);
            #pragma unroll
            for (int mi=0;mi<2;mi++)
                #pragma unroll
                for (int ni=0;ni<4;ni++)
                    wmma::mma_sync(acc[mi][ni], af[mi], bf[ni], acc[mi][ni]);
        }
    }

    __syncthreads();
    float* ep = (float*)smem;
    #pragma unroll
    for (int mi=0;mi<2;mi++)
        #pragma unroll
        for (int ni=0;ni<4;ni++)
            wmma::store_matrix_sync(ep + (wm*32+mi*16)*EPLD + wn*64 + ni*16,
                                    acc[mi][ni], EPLD, wmma::mem_row_major);
    __syncthreads();
    {
        const int er  = tid >> 5;
        const int ec4 = (tid & 31) * 4;
        float4 bb = *(const float4*)(bias + n0 + ec4);
        #pragma unroll
        for (int p=0;p<16;p++){
            int r = p*8 + er;
            float4 v = *(float4*)(ep + r*EPLD + ec4);
            v.x = (v.x + bb.x) * scale;
            v.y = (v.y + bb.y) * scale;
            v.z = (v.z + bb.z) * scale;
            v.w = (v.w + bb.w) * scale;
            if (Ch){
                __half2 h0 = __floats2half2_rn(v.x, v.y);
                __half2 h1 = __floats2half2_rn(v.z, v.w);
                __half2* dst = (__half2*)(Ch + (size_t)(m0 + r)*HID + n0 + ec4);
                dst[0] = h0; dst[1] = h1;
            } else {
                *(float4*)(Cf + (size_t)(m0 + r)*HID + n0 + ec4) = v;
            }
        }
    }
}

__global__ void __launch_bounds__(256,2)
qkv_proj_kernel(const float* __restrict__ bq, const float* __restrict__ bk,
                const float* __restrict__ bv)
{
    extern __shared__ char smem[];
    const int z = blockIdx.z;
    const __half* A    = (z==0) ? g_Xq  : (z==1) ? g_Xk  : g_Xv;
    const __half* W    = (z==0) ? g_Wqh : (z==1) ? g_Wkh : g_Wvh;
    const float* bias  = (z==0) ? bq : (z==1) ? bk : bv;
    __half*      C     = (z==0) ? g_Qh : (z==1) ? g_Kh : g_Vh;
    const float scale  = (z==0) ? 0.125f : 1.0f;
    proj_body_h(A, W, bias, scale, nullptr, C, smem);
}

__global__ void __launch_bounds__(256,2)
out_proj_kernel(const float* __restrict__ bo, float* __restrict__ C)
{
    extern __shared__ char smem[];
    proj_body_h(g_Oh, g_Woh, bo, 1.0f, C, nullptr, smem);
}

// ===========================================================================
// FA2-style fused attention (R15 structure), fixed-shift softmax,
// raw mma.sync + ldmatrix. CTA = 256 threads (8 warps), 32 query rows,
// 4 CTAs/SM (ptxas targets <=64 regs via launch bounds).
// Pass A: E chunks -> exp in registers -> row sums only.
// Pass B: recompute E, p -> exact fp32 P to gmem; fp16 P tile staged in SMEM;
//         each warp accumulates its DISJOINT 16x16 O block over full k=64.
// ===========================================================================
#define STRIPE 32
#define CH     64
#define NCHUNK (SEQ/CH)        // 16
// SMEM layout (bytes); K/V/Q/P rows are 144 B (72 halves)
#define AS_Q    0                      // 32*144 = 4608
#define AS_K    4608                   // 2 * 64*144 = 18432
#define AS_V    23040                  // 2 * 64*144 = 18432
#define AS_P    41472                  // 32*144 = 4608
#define AS_M    46080                  // 4096
#define AS_SP   50176                  // 4*32 floats = 512
#define AS_RI   50688                  // 32 floats = 128
#define FUSED_SMEM_BYTES 50816

__global__ void __launch_bounds__(256,4)
fused_attn_kernel(float* __restrict__ attn, const int* __restrict__ mask)
{
    extern __shared__ char smc[];
    const unsigned sbase = (unsigned)__cvta_generic_to_shared(smc);

    const int tid  = threadIdx.x;
    const int warp = tid >> 5;
    const int lane = tid & 31;
    const int wm   = warp & 1;
    const int wn   = warp >> 1;          // 0..3

    const int blk  = blockIdx.x;
    const int bh   = blk >> 5;
    const int strp = blk & 31;
    const int b    = bh >> 4;
    const int h    = bh & 15;
    const int m0   = strp * STRIPE;

    const __half* Qb = g_Qh + ((size_t)b*SEQ + m0)*HID + h*HDIM;
    const __half* Kg = g_Kh + (size_t)b*SEQ*HID + h*HDIM;
    const __half* Vg = g_Vh + (size_t)b*SEQ*HID + h*HDIM;

    // ---- fills: mask (plain stores), Q stripe + K chunk 0 (cp.async) ----
    *(int4*)(smc + AS_M + tid*16) = ((const int4*)(mask + b*SEQ))[tid];
    {
        const int r  = tid >> 3;
        const int ch = tid & 7;
        cp_async16(smc + AS_Q + r*144 + ch*16, Qb + (size_t)r*HID + ch*8);
        #pragma unroll
        for (int p=0;p<2;p++){
            const int idx = tid + p*256;
            const int kr  = idx >> 3;
            const int kc  = idx & 7;
            cp_async16(smc + AS_K + kr*144 + kc*16, Kg + (size_t)kr*HID + kc*8);
        }
        CP_COMMIT();
    }
    CP_WAIT0();
    __syncthreads();

    // ---- mask bitset per lane ----
    uint64_t mb = 0;
    {
        const int* Msp = (const int*)(smc + AS_M);
        const int cb = wn*16 + (lane&3)*2;
        #pragma unroll
        for (int c=0;c<NCHUNK;c++)
            #pragma unroll
            for (int t=0;t<2;t++)
                #pragma unroll
                for (int j=0;j<2;j++)
                    if (Msp[c*64 + cb + t*8 + j])
                        mb |= 1ull << (c*4 + t*2 + j);
    }

    // ---- Q fragments: loaded ONCE ----
    const int qrow = (lane & 7) + ((lane >> 3) & 1)*8;
    const int qcB  = ((lane >> 4) & 1)*16;
    unsigned qa[4][4];
    {
        const unsigned qaddr = sbase + AS_Q + (wm*16 + qrow)*144 + qcB;
        #pragma unroll
        for (int s=0;s<4;s++)
            LDMX4(qa[s][0], qa[s][1], qa[s][2], qa[s][3], qaddr + s*32);
    }

    // K ldmatrix lane addressing
    const int knoff = (lane & 7) | ((lane >> 1) & 8);
    const int kB    = ((lane >> 3) & 1)*16;
    const unsigned kbase_l = (wn*16 + knoff)*144 + kB;

    // ================= Pass A: row sums of exp(E) =================
    float s0 = 0.0f, s1 = 0.0f;
    for (int c=0;c<NCHUNK;c++){
        if (c+1 < NCHUNK){
            const __half* src = Kg + (size_t)((c+1)*CH)*HID;
            char* dst = smc + AS_K + ((c+1)&1)*9216;
            #pragma unroll
            for (int p=0;p<2;p++){
                const int idx = tid + p*256;
                const int kr  = idx >> 3;
                const int kc  = idx & 7;
                cp_async16(dst + kr*144 + kc*16, src + (size_t)kr*HID + kc*8);
            }
            CP_COMMIT();
        } else {
            // prefetch pass-B chunk 0: K0 -> kbuf0, V0 -> vbuf0
            #pragma unroll
            for (int p=0;p<2;p++){
                const int idx = tid + p*256;
                const int kr  = idx >> 3;
                const int kc  = idx & 7;
                cp_async16(smc + AS_K + kr*144 + kc*16, Kg + (size_t)kr*HID + kc*8);
                cp_async16(smc + AS_V + kr*144 + kc*16, Vg + (size_t)kr*HID + kc*8);
            }
            CP_COMMIT();
        }

        const unsigned kaddr = sbase + AS_K + (c&1)*9216 + kbase_l;
        float acc0[4] = {0,0,0,0};
        float acc1[4] = {0,0,0,0};
        #pragma unroll
        for (int s=0;s<4;s++){
            unsigned k0,k1,k2,k3;
            LDMX4(k0,k1,k2,k3, kaddr + s*32);
            MMA16816(acc0, qa[s][0],qa[s][1],qa[s][2],qa[s][3], k0,k1);
            MMA16816(acc1, qa[s][0],qa[s][1],qa[s][2],qa[s][3], k2,k3);
        }
        {
            const unsigned mbits = (unsigned)(mb >> (c*4)) & 0xFu;
            float p00 = (mbits & 1u) ? __expf(acc0[0]) : 0.0f;
            float p01 = (mbits & 2u) ? __expf(acc0[1]) : 0.0f;
            float p02 = (mbits & 1u) ? __expf(acc0[2]) : 0.0f;
            float p03 = (mbits & 2u) ? __expf(acc0[3]) : 0.0f;
            float p10 = (mbits & 4u) ? __expf(acc1[0]) : 0.0f;
            float p11 = (mbits & 8u) ? __expf(acc1[1]) : 0.0f;
            float p12 = (mbits & 4u) ? __expf(acc1[2]) : 0.0f;
            float p13 = (mbits & 8u) ? __expf(acc1[3]) : 0.0f;
            s0 += (p00 + p01) + (p10 + p11);
            s1 += (p02 + p03) + (p12 + p13);
        }
        CP_WAIT0();
        __syncthreads();
    }

    // ---- row-sum reduction ----
    s0 += __shfl_xor_sync(0xffffffffu, s0, 1);
    s0 += __shfl_xor_sync(0xffffffffu, s0, 2);
    s1 += __shfl_xor_sync(0xffffffffu, s1, 1);
    s1 += __shfl_xor_sync(0xffffffffu, s1, 2);
    float* Sp   = (float*)(smc + AS_SP);
    float* rowI = (float*)(smc + AS_RI);
    if ((lane & 3) == 0){
        Sp[wn*32 + wm*16 +     (lane>>2)] = s0;
        Sp[wn*32 + wm*16 + 8 + (lane>>2)] = s1;
    }
    __syncthreads();
    if (tid < 32)
        rowI[tid] = 1.0f / (Sp[tid] + Sp[32+tid] + Sp[64+tid] + Sp[96+tid]);
    __syncthreads();

    const float rI0 = rowI[wm*16 +     (lane>>2)];
    const float rI1 = rowI[wm*16 + 8 + (lane>>2)];

    // ================= Pass B: recompute E, write P, PV =================
    float oacc0[4] = {0,0,0,0};
    float oacc1[4] = {0,0,0,0};
    const int vrow = (lane & 7) + ((lane >> 3) & 1)*8;
    const int grow = wm*16 + (lane>>2);
    const int colb = wn*16 + (lane&3)*2;
    float* attnR0 = attn + ((size_t)bh*SEQ + m0 + grow)*SEQ;
    float* attnR1 = attnR0 + (size_t)8*SEQ;

    for (int c=0;c<NCHUNK;c++){
        if (c+1 < NCHUNK){
            const __half* ksrc = Kg + (size_t)((c+1)*CH)*HID;
            const __half* vsrc = Vg + (size_t)((c+1)*CH)*HID;
            char* kdst = smc + AS_K + ((c+1)&1)*9216;
            char* vdst = smc + AS_V + ((c+1)&1)*9216;
            #pragma unroll
            for (int p=0;p<2;p++){
                const int idx = tid + p*256;
                const int kr  = idx >> 3;
                const int kc  = idx & 7;
                cp_async16(kdst + kr*144 + kc*16, ksrc + (size_t)kr*HID + kc*8);
                cp_async16(vdst + kr*144 + kc*16, vsrc + (size_t)kr*HID + kc*8);
            }
            CP_COMMIT();
        }

        // QK recompute (deterministic)
        const unsigned kaddr = sbase + AS_K + (c&1)*9216 + kbase_l;
        float acc0[4] = {0,0,0,0};
        float acc1[4] = {0,0,0,0};
        #pragma unroll
        for (int s=0;s<4;s++){
            unsigned k0,k1,k2,k3;
            LDMX4(k0,k1,k2,k3, kaddr + s*32);
            MMA16816(acc0, qa[s][0],qa[s][1],qa[s][2],qa[s][3], k0,k1);
            MMA16816(acc1, qa[s][0],qa[s][1],qa[s][2],qa[s][3], k2,k3);
        }

        // p = exp(e)*inv -> exact fp32 attn; fp16 tile to SMEM
        {
            const unsigned mbits = (unsigned)(mb >> (c*4)) & 0xFu;
            float p00 = (mbits & 1u) ? __expf(acc0[0])*rI0 : 0.0f;
            float p01 = (mbits & 2u) ? __expf(acc0[1])*rI0 : 0.0f;
            float p02 = (mbits & 1u) ? __expf(acc0[2])*rI1 : 0.0f;
            float p03 = (mbits & 2u) ? __expf(acc0[3])*rI1 : 0.0f;
            float p10 = (mbits & 4u) ? __expf(acc1[0])*rI0 : 0.0f;
            float p11 = (mbits & 8u) ? __expf(acc1[1])*rI0 : 0.0f;
            float p12 = (mbits & 4u) ? __expf(acc1[2])*rI1 : 0.0f;
            float p13 = (mbits & 8u) ? __expf(acc1[3])*rI1 : 0.0f;
            const int cb = c*64 + colb;
            *(float2*)(attnR0 + cb)     = make_float2(p00, p01);
            *(float2*)(attnR1 + cb)     = make_float2(p02, p03);
            *(float2*)(attnR0 + cb + 8) = make_float2(p10, p11);
            *(float2*)(attnR1 + cb + 8) = make_float2(p12, p13);
            __half2 h0 = __floats2half2_rn(p00, p01);
            __half2 h1 = __floats2half2_rn(p02, p03);
            __half2 h2 = __floats2half2_rn(p10, p11);
            __half2 h3 = __floats2half2_rn(p12, p13);
            *(__half2*)(smc + AS_P + grow*144     + colb*2)       = h0;
            *(__half2*)(smc + AS_P + (grow+8)*144 + colb*2)       = h1;
            *(__half2*)(smc + AS_P + grow*144     + (colb+8)*2)   = h2;
            *(__half2*)(smc + AS_P + (grow+8)*144 + (colb+8)*2)   = h3;
        }
        __syncthreads();   // P tile complete (QK reads of K[c] also done)

        // PV: O[wm*16.., wn*16..16] += P(16x64, full) @ V(64, wn-slice 16)
        {
            const unsigned paddr = sbase + AS_P + (wm*16 + qrow)*144 + qcB;
            const unsigned vbase = sbase + AS_V + (c&1)*9216;
            #pragma unroll
            for (int kk=0;kk<4;kk++){
                unsigned p0,p1,p2,p3;
                LDMX4(p0,p1,p2,p3, paddr + kk*32);
                unsigned v0,v1,w0,w1;
                LDMX2T(v0,v1, vbase + (kk*16+vrow)*144 + wn*32);
                LDMX2T(w0,w1, vbase + (kk*16+vrow)*144 + wn*32 + 16);
                MMA16816(oacc0, p0,p1,p2,p3, v0,v1);
                MMA16816(oacc1, p0,p1,p2,p3, w0,w1);
            }
        }
        CP_WAIT0();
        __syncthreads();   // P free for next chunk; K/V[c+1] ready
    }

    // ---- O epilogue: each warp owns disjoint 16x16 block ----
    {
        __half2 a0 = __floats2half2_rn(oacc0[0], oacc0[1]);
        __half2 a1 = __floats2half2_rn(oacc0[2], oacc0[3]);
        __half2 a2 = __floats2half2_rn(oacc1[0], oacc1[1]);
        __half2 a3 = __floats2half2_rn(oacc1[2], oacc1[3]);
        __half* base0 = g_Oh + (size_t)(b*SEQ + m0 + grow)*HID + h*HDIM;
        __half* base1 = g_Oh + (size_t)(b*SEQ + m0 + grow + 8)*HID + h*HDIM;
        *(__half2*)(base0 + colb)     = a0;
        *(__half2*)(base1 + colb)     = a1;
        *(__half2*)(base0 + colb + 8) = a2;
        *(__half2*)(base1 + colb + 8) = a3;
    }
}

// ---------------------------------------------------------------------------
extern "C" void kernel_launch(void* const* d_in, const int* in_sizes, int n_in,
                              void* d_out, int out_size)
{
    const float* query = (const float*)d_in[0];
    const float* key   = (const float*)d_in[1];
    const float* value = (const float*)d_in[2];
    const float* Wq    = (const float*)d_in[3];
    const float* bq    = (const float*)d_in[4];
    const float* Wk    = (const float*)d_in[5];
    const float* bk    = (const float*)d_in[6];
    const float* Wv    = (const float*)d_in[7];
    const float* bv    = (const float*)d_in[8];
    const float* Wo    = (const float*)d_in[9];
    const float* bo    = (const float*)d_in[10];
    const int*   mask  = (const int*)d_in[11];

    float* out_x = (float*)d_out;
    float* attn  = out_x + (size_t)MROWS * HID;

    __half *xq, *xk, *xv, *wqh, *wkh, *wvh, *woh;
    cudaGetSymbolAddress((void**)&xq, g_Xq);
    cudaGetSymbolAddress((void**)&xk, g_Xk);
    cudaGetSymbolAddress((void**)&xv, g_Xv);
    cudaGetSymbolAddress((void**)&wqh, g_Wqh);
    cudaGetSymbolAddress((void**)&wkh, g_Wkh);
    cudaGetSymbolAddress((void**)&wvh, g_Wvh);
    cudaGetSymbolAddress((void**)&woh, g_Woh);

    static int attr_done = 0;
    if (!attr_done){
        cudaFuncSetAttribute(qkv_proj_kernel,
            cudaFuncAttributeMaxDynamicSharedMemorySize, PROJ_SMEM_BYTES);
        cudaFuncSetAttribute(out_proj_kernel,
            cudaFuncAttributeMaxDynamicSharedMemorySize, PROJ_SMEM_BYTES);
        cudaFuncSetAttribute(fused_attn_kernel,
            cudaFuncAttributeMaxDynamicSharedMemorySize, FUSED_SMEM_BYTES);
        attr_done = 1;
    }

    // fp32 -> fp16 conversions (inputs + weights)
    dim3 gact(MROWS*HID/(256*8), 1, 3);   // (4096,1,3)
    dim3 gw(HID*HID/(256*8), 1, 4);       // (512,1,4)
    cvt_act_kernel<<<gact, 256>>>(query, key, value, xq, xk, xv);
    cvt_w_kernel<<<gw, 256>>>(Wq, Wk, Wv, Wo, wqh, wkh, wvh, woh);

    dim3 gqkv(HID/TBN, MROWS/TBM, 3);   // (8, 64, 3)
    dim3 gproj(HID/TBN, MROWS/TBM);     // (8, 64)

    // Q/K/V projections (1/sqrt(64) folded into Q); half outputs
    qkv_proj_kernel<<<gqkv, 256, PROJ_SMEM_BYTES>>>(bq, bk, bv);

    // FA2-style fused attention (exact attention to d_out)
    fused_attn_kernel<<<BHS/STRIPE, 256, FUSED_SMEM_BYTES>>>(attn, mask);

    // x = O Wo^T + bo (exact fp32 output)
    out_proj_kernel<<<gproj, 256, PROJ_SMEM_BYTES>>>(bo, out_x);
}